// round 1
// baseline (speedup 1.0000x reference)
#include <cuda_runtime.h>
#include <cuda_bf16.h>
#include <cstdint>

// Problem constants (fixed by the reference: B=4, T=2048, C=1024, H=16)
#define B_  4
#define T_  2048
#define C_  1024
#define H_  16
#define HS_ 64
#define M_  (B_ * T_)     // 8192 rows of x
#define N3_ (3 * C_)      // 3072 output features of QKV
#define K_  C_            // 1024 reduction dim

// Scratch: q/k/v in [B, H, T, hs] layout. __device__ globals (no allocation).
__device__ float g_q[(size_t)B_ * H_ * T_ * HS_];
__device__ float g_k[(size_t)B_ * H_ * T_ * HS_];
__device__ float g_v[(size_t)B_ * H_ * T_ * HS_];

// ---------------------------------------------------------------------------
// Kernel 1: fused QKV projection.  C[m,n] = sum_k x[m,k] * W[n,k] + b[n]
// (x row-major [M,K], W row-major [3C, K] -> NT GEMM, both K-contiguous)
// Output scattered directly into g_q / g_k / g_v in [B,H,T,hs] layout.
// ---------------------------------------------------------------------------
__global__ __launch_bounds__(256)
void qkv_gemm_kernel(const float* __restrict__ A,
                     const float* __restrict__ W,
                     const float* __restrict__ bias) {
    constexpr int BM = 128, BN = 128, BK = 16;
    __shared__ float As[BK][BM];   // transposed: As[k][m]
    __shared__ float Bs[BK][BN];   // transposed: Bs[k][n]

    const int tid  = threadIdx.x;          // 0..255
    const int tx   = tid & 15;              // N direction (16)
    const int ty   = tid >> 4;              // M direction (16)
    const int row0 = blockIdx.y * BM;
    const int col0 = blockIdx.x * BN;

    float acc[8][8];
#pragma unroll
    for (int i = 0; i < 8; i++)
#pragma unroll
        for (int j = 0; j < 8; j++) acc[i][j] = 0.0f;

    for (int k0 = 0; k0 < K_; k0 += BK) {
        // Cooperative loads: 128 rows x 16 k = 512 float4 per operand,
        // 2 float4 per thread per operand.
#pragma unroll
        for (int p = 0; p < 2; p++) {
            int idx = tid + p * 256;        // 0..511
            int r   = idx >> 2;             // 0..127
            int kk  = (idx & 3) << 2;       // 0,4,8,12
            float4 va = *(const float4*)(A + (size_t)(row0 + r) * K_ + k0 + kk);
            As[kk + 0][r] = va.x; As[kk + 1][r] = va.y;
            As[kk + 2][r] = va.z; As[kk + 3][r] = va.w;
            float4 vb = *(const float4*)(W + (size_t)(col0 + r) * K_ + k0 + kk);
            Bs[kk + 0][r] = vb.x; Bs[kk + 1][r] = vb.y;
            Bs[kk + 2][r] = vb.z; Bs[kk + 3][r] = vb.w;
        }
        __syncthreads();

#pragma unroll
        for (int kk = 0; kk < BK; kk++) {
            float4 a0 = *(const float4*)&As[kk][ty * 8];
            float4 a1 = *(const float4*)&As[kk][ty * 8 + 4];
            float4 b0 = *(const float4*)&Bs[kk][tx * 8];
            float4 b1 = *(const float4*)&Bs[kk][tx * 8 + 4];
            float ra[8] = {a0.x, a0.y, a0.z, a0.w, a1.x, a1.y, a1.z, a1.w};
            float rb[8] = {b0.x, b0.y, b0.z, b0.w, b1.x, b1.y, b1.z, b1.w};
#pragma unroll
            for (int i = 0; i < 8; i++)
#pragma unroll
                for (int j = 0; j < 8; j++)
                    acc[i][j] += ra[i] * rb[j];
        }
        __syncthreads();
    }

    // Epilogue: add bias, scatter to q/k/v in [B,H,T,hs] layout.
    float rbias[8];
#pragma unroll
    for (int j = 0; j < 8; j++) rbias[j] = bias[col0 + tx * 8 + j];

#pragma unroll
    for (int i = 0; i < 8; i++) {
        int m    = row0 + ty * 8 + i;
        int bidx = m >> 11;            // m / T_
        int t    = m & (T_ - 1);
#pragma unroll
        for (int j = 0; j < 8; j++) {
            int n = col0 + tx * 8 + j;
            float val = acc[i][j] + rbias[j];
            int s = n >> 10;           // 0:q 1:k 2:v
            int h = (n >> 6) & (H_ - 1);
            int d = n & (HS_ - 1);
            float* dst = (s == 0) ? g_q : ((s == 1) ? g_k : g_v);
            dst[(((size_t)bidx * H_ + h) * T_ + t) * HS_ + d] = val;
        }
    }
}

// ---------------------------------------------------------------------------
// Kernel 2: causal flash attention, fp32.
// Grid: (T/64 query tiles, B*H). Block: 256 threads, 4x4 micro-tiles.
// Smem (dynamic, pitch 68 for bank behavior + 16B alignment):
//   Qt[d][r]  (transposed Q tile)     64x68
//   Kt[d][c]  (transposed K tile)     64x68
//   Vs[k][d]  (natural V tile)        64x68
//   Pt[k][r]  (transposed P tile)     64x68
// ---------------------------------------------------------------------------
#define FA_PITCH 68
#define FA_SMEM_BYTES (4 * 64 * FA_PITCH * 4)

__global__ __launch_bounds__(256)
void flash_attn_kernel(float* __restrict__ out) {
    extern __shared__ float sm[];
    float* Qt = sm;                       // [64][68]
    float* Kt = Qt + 64 * FA_PITCH;
    float* Vs = Kt + 64 * FA_PITCH;
    float* Pt = Vs + 64 * FA_PITCH;

    const int tid = threadIdx.x;
    const int tx  = tid & 15;             // key/dim direction
    const int ty  = tid >> 4;             // query-row direction
    const int bh  = blockIdx.y;           // 0..63
    const int b   = bh >> 4;
    const int h   = bh & (H_ - 1);
    const int qt  = gridDim.x - 1 - blockIdx.x;   // biggest tiles first
    const int q0  = qt * 64;
    const float scale = 0.125f;           // hs^-0.5 = 1/8

    const size_t base = (size_t)bh * T_ * HS_;

    // Load Q tile transposed: Qt[d][r]
#pragma unroll
    for (int p = 0; p < 4; p++) {
        int idx = tid + p * 256;           // 0..1023 float4 slots
        int r   = idx >> 4;                // 0..63
        int d   = (idx & 15) << 2;         // 0..60
        float4 v = *(const float4*)(g_q + base + (size_t)(q0 + r) * HS_ + d);
        Qt[(d + 0) * FA_PITCH + r] = v.x;
        Qt[(d + 1) * FA_PITCH + r] = v.y;
        Qt[(d + 2) * FA_PITCH + r] = v.z;
        Qt[(d + 3) * FA_PITCH + r] = v.w;
    }

    float m_[4], l_[4], o_[4][4];
#pragma unroll
    for (int i = 0; i < 4; i++) {
        m_[i] = -1e30f; l_[i] = 0.0f;
#pragma unroll
        for (int j = 0; j < 4; j++) o_[i][j] = 0.0f;
    }

    for (int kt = 0; kt <= qt; kt++) {
        const int k0 = kt * 64;
        __syncthreads();   // Qt visible (iter 0); prior PV done before overwrite

        // Load K transposed + V natural
#pragma unroll
        for (int p = 0; p < 4; p++) {
            int idx = tid + p * 256;
            int r   = idx >> 4;
            int d   = (idx & 15) << 2;
            float4 kv = *(const float4*)(g_k + base + (size_t)(k0 + r) * HS_ + d);
            Kt[(d + 0) * FA_PITCH + r] = kv.x;
            Kt[(d + 1) * FA_PITCH + r] = kv.y;
            Kt[(d + 2) * FA_PITCH + r] = kv.z;
            Kt[(d + 3) * FA_PITCH + r] = kv.w;
            float4 vv = *(const float4*)(g_v + base + (size_t)(k0 + r) * HS_ + d);
            *(float4*)&Vs[r * FA_PITCH + d] = vv;
        }
        __syncthreads();

        // S = scale * Q K^T  (4x4 per thread)
        float s[4][4];
#pragma unroll
        for (int i = 0; i < 4; i++)
#pragma unroll
            for (int j = 0; j < 4; j++) s[i][j] = 0.0f;

#pragma unroll 8
        for (int d = 0; d < 64; d++) {
            float4 qv = *(const float4*)&Qt[d * FA_PITCH + ty * 4];
            float4 kv = *(const float4*)&Kt[d * FA_PITCH + tx * 4];
            float qa[4] = {qv.x, qv.y, qv.z, qv.w};
            float ka[4] = {kv.x, kv.y, kv.z, kv.w};
#pragma unroll
            for (int i = 0; i < 4; i++)
#pragma unroll
                for (int j = 0; j < 4; j++)
                    s[i][j] += qa[i] * ka[j];
        }

        // scale + causal mask (diagonal tile only)
#pragma unroll
        for (int i = 0; i < 4; i++) {
#pragma unroll
            for (int j = 0; j < 4; j++) {
                s[i][j] *= scale;
                if (kt == qt && (tx * 4 + j) > (ty * 4 + i)) s[i][j] = -1e30f;
            }
        }

        // Online softmax update. Row r is owned by the 16 lanes sharing ty;
        // xor-shuffles over lane bits 0..3 reduce within that group.
        float nm[4], alpha[4];
#pragma unroll
        for (int i = 0; i < 4; i++) {
            float rmax = fmaxf(fmaxf(s[i][0], s[i][1]), fmaxf(s[i][2], s[i][3]));
#pragma unroll
            for (int off = 8; off > 0; off >>= 1)
                rmax = fmaxf(rmax, __shfl_xor_sync(0xffffffffu, rmax, off));
            nm[i] = fmaxf(m_[i], rmax);

            float rsum = 0.0f;
#pragma unroll
            for (int j = 0; j < 4; j++) {
                s[i][j] = __expf(s[i][j] - nm[i]);   // now p
                rsum += s[i][j];
            }
#pragma unroll
            for (int off = 8; off > 0; off >>= 1)
                rsum += __shfl_xor_sync(0xffffffffu, rsum, off);

            alpha[i] = __expf(m_[i] - nm[i]);
            l_[i] = l_[i] * alpha[i] + rsum;
            m_[i] = nm[i];
#pragma unroll
            for (int j = 0; j < 4; j++) o_[i][j] *= alpha[i];
        }

        // Stage P transposed: Pt[key][row]
#pragma unroll
        for (int j = 0; j < 4; j++) {
            float4 pv = make_float4(s[0][j], s[1][j], s[2][j], s[3][j]);
            *(float4*)&Pt[(tx * 4 + j) * FA_PITCH + ty * 4] = pv;
        }
        __syncthreads();

        // O += P V
#pragma unroll 8
        for (int kk = 0; kk < 64; kk++) {
            float4 pv = *(const float4*)&Pt[kk * FA_PITCH + ty * 4];
            float4 vv = *(const float4*)&Vs[kk * FA_PITCH + tx * 4];
            float pa[4] = {pv.x, pv.y, pv.z, pv.w};
            float va[4] = {vv.x, vv.y, vv.z, vv.w};
#pragma unroll
            for (int i = 0; i < 4; i++)
#pragma unroll
                for (int j = 0; j < 4; j++)
                    o_[i][j] += pa[i] * va[j];
        }
    }

    // Finalize + write out[b, t, h*64 + d]
#pragma unroll
    for (int i = 0; i < 4; i++) {
        float inv = 1.0f / l_[i];
        int t = q0 + ty * 4 + i;
        float4 res = make_float4(o_[i][0] * inv, o_[i][1] * inv,
                                 o_[i][2] * inv, o_[i][3] * inv);
        *(float4*)(out + ((size_t)(b * T_ + t) * C_) + h * HS_ + tx * 4) = res;
    }
}

// ---------------------------------------------------------------------------
extern "C" void kernel_launch(void* const* d_in, const int* in_sizes, int n_in,
                              void* d_out, int out_size) {
    const float* x    = (const float*)d_in[0];
    const float* W    = (const float*)d_in[1];
    const float* bias = (const float*)d_in[2];
    // d_in[3] = input_pos (unused, cache=False path)
    float* out = (float*)d_out;

    // Opt in to >48KB dynamic smem (idempotent host call; capture-legal).
    cudaFuncSetAttribute(flash_attn_kernel,
                         cudaFuncAttributeMaxDynamicSharedMemorySize,
                         FA_SMEM_BYTES);

    dim3 g1(N3_ / 128, M_ / 128);       // 24 x 64
    qkv_gemm_kernel<<<g1, 256>>>(x, W, bias);

    dim3 g2(T_ / 64, B_ * H_);          // 32 x 64
    flash_attn_kernel<<<g2, 256, FA_SMEM_BYTES>>>(out);
}

// round 3
// speedup vs baseline: 3.6250x; 3.6250x over previous
#include <cuda_runtime.h>
#include <cstdint>

// Problem constants (fixed: B=4, T=2048, C=1024, H=16)
#define B_  4
#define T_  2048
#define C_  1024
#define H_  16
#define HS_ 64
#define M_  (B_ * T_)     // 8192
#define N3_ (3 * C_)      // 3072
#define K_  C_            // 1024

// Scratch (__device__ globals: no allocation at runtime).
__device__ float g_q[(size_t)B_ * H_ * T_ * HS_];
__device__ float g_k[(size_t)B_ * H_ * T_ * HS_];
__device__ float g_v[(size_t)B_ * H_ * T_ * HS_];
__device__ float g_xr[(size_t)M_ * K_];    // tf32-rounded x
__device__ float g_wr[(size_t)N3_ * K_];   // tf32-rounded W

// ---------------------------------------------------------------------------
// Helpers
// ---------------------------------------------------------------------------
__device__ __forceinline__ uint32_t smem_u32(const void* p) {
    uint32_t a;
    asm("{ .reg .u64 t; cvta.to.shared.u64 t, %1; cvt.u32.u64 %0, t; }"
        : "=r"(a) : "l"(p));
    return a;
}

// Round f32 -> tf32 (round-to-nearest) returning f32 bits with low 13 bits 0.
__device__ __forceinline__ float to_tf32(float x) {
    uint32_t u;
    asm("cvt.rna.tf32.f32 %0, %1;" : "=r"(u) : "f"(x));
    return __uint_as_float(u);
}

__device__ __forceinline__ void ldsm4(uint32_t& r0, uint32_t& r1,
                                      uint32_t& r2, uint32_t& r3, uint32_t addr) {
    asm volatile("ldmatrix.sync.aligned.m8n8.x4.shared.b16 {%0,%1,%2,%3}, [%4];"
                 : "=r"(r0), "=r"(r1), "=r"(r2), "=r"(r3) : "r"(addr));
}

__device__ __forceinline__ void mma_tf32(float* c, const uint32_t* a,
                                         uint32_t b0, uint32_t b1) {
    asm volatile(
        "mma.sync.aligned.m16n8k8.row.col.f32.tf32.tf32.f32 "
        "{%0,%1,%2,%3}, {%4,%5,%6,%7}, {%8,%9}, {%0,%1,%2,%3};"
        : "+f"(c[0]), "+f"(c[1]), "+f"(c[2]), "+f"(c[3])
        : "r"(a[0]), "r"(a[1]), "r"(a[2]), "r"(a[3]), "r"(b0), "r"(b1));
}

__device__ __forceinline__ void cp16(uint32_t dst_smem, const void* src) {
    asm volatile("cp.async.cg.shared.global [%0], [%1], 16;"
                 :: "r"(dst_smem), "l"(src));
}

// ---------------------------------------------------------------------------
// Kernel 0: round x and W to tf32 into scratch (unbiased operands for GEMM).
// ---------------------------------------------------------------------------
#define NX4 (M_ * K_ / 4)
#define NW4 (N3_ * K_ / 4)

__global__ __launch_bounds__(256)
void round_inputs(const float* __restrict__ x, const float* __restrict__ W) {
    int i = blockIdx.x * 256 + threadIdx.x;
    if (i < NX4) {
        float4 v = ((const float4*)x)[i];
        v.x = to_tf32(v.x); v.y = to_tf32(v.y);
        v.z = to_tf32(v.z); v.w = to_tf32(v.w);
        ((float4*)g_xr)[i] = v;
    } else {
        int j = i - NX4;
        float4 v = ((const float4*)W)[j];
        v.x = to_tf32(v.x); v.y = to_tf32(v.y);
        v.z = to_tf32(v.z); v.w = to_tf32(v.w);
        ((float4*)g_wr)[j] = v;
    }
}

// ---------------------------------------------------------------------------
// Kernel 1: QKV GEMM, tf32 mma.sync.  D[m,n] = sum_k x[m,k]*W[n,k] + b[n]
// CTA 128x128, BK=32, 8 warps (2x4), 3-stage cp.async, pitch-36 smem.
// ---------------------------------------------------------------------------
#define GP 36                               // smem pitch in floats
#define GM_STAGE_FLT (2 * 128 * GP)         // 9216 floats / stage
#define GM_SMEM_BYTES (3 * GM_STAGE_FLT * 4)  // 110592 B
#define GM_KT (K_ / 32)                     // 32

__global__ __launch_bounds__(256)
void qkv_gemm_tc(const float* __restrict__ bias) {
    extern __shared__ float sm[];
    const int tid  = threadIdx.x;
    const int lane = tid & 31;
    const int w    = tid >> 5;
    const int wm   = w >> 2;                 // 0..1  (64 rows)
    const int wn   = w & 3;                  // 0..3  (32 cols)
    const int row0 = blockIdx.y * 128;
    const int col0 = blockIdx.x * 128;

    float acc[4][4][4];
#pragma unroll
    for (int i = 0; i < 4; i++)
#pragma unroll
        for (int j = 0; j < 4; j++)
#pragma unroll
            for (int e = 0; e < 4; e++) acc[i][j][e] = 0.0f;

    // ---- staging ----
    const int lr = tid >> 3;                 // 0..31 row step base
    const int lc = (tid & 7) * 4;            // float col within 32
#define GM_LOAD(kt) do {                                                       \
    int s_ = (kt) % 3;                                                         \
    float* sA_ = sm + s_ * GM_STAGE_FLT;                                       \
    float* sB_ = sA_ + 128 * GP;                                               \
    uint32_t aOff_ = smem_u32(sA_), bOff_ = smem_u32(sB_);                     \
    const float* Ab_ = g_xr + (size_t)row0 * K_ + (kt) * 32;                   \
    const float* Bb_ = g_wr + (size_t)col0 * K_ + (kt) * 32;                   \
    _Pragma("unroll")                                                          \
    for (int q_ = 0; q_ < 4; q_++) {                                           \
        int r_ = lr + q_ * 32;                                                 \
        cp16(aOff_ + (r_ * GP + lc) * 4, Ab_ + (size_t)r_ * K_ + lc);          \
        cp16(bOff_ + (r_ * GP + lc) * 4, Bb_ + (size_t)r_ * K_ + lc);          \
    }                                                                          \
    asm volatile("cp.async.commit_group;" ::: "memory");                       \
} while (0)

    GM_LOAD(0);
    GM_LOAD(1);

    // fragment lane offsets
    const int aRow  = lane & 15;
    const int aCol  = (lane >> 4) * 4;
    const int bRowO = ((lane & 16) ? 8 : 0) + (lane & 7);
    const int bColO = (lane & 8) ? 4 : 0;

    for (int kt = 0; kt < GM_KT; kt++) {
        if (kt + 1 < GM_KT) asm volatile("cp.async.wait_group 1;" ::: "memory");
        else                asm volatile("cp.async.wait_group 0;" ::: "memory");
        __syncthreads();

        const float* sA = sm + (kt % 3) * GM_STAGE_FLT;
        const uint32_t aBase = smem_u32(sA);
        const uint32_t bBase = aBase + 128 * GP * 4;

#pragma unroll
        for (int ks = 0; ks < 4; ks++) {
            const int kc = ks * 8;
            uint32_t a[4][4];
#pragma unroll
            for (int i = 0; i < 4; i++) {
                int row = wm * 64 + i * 16 + aRow;
                ldsm4(a[i][0], a[i][1], a[i][2], a[i][3],
                      aBase + (row * GP + kc + aCol) * 4);
            }
            uint32_t bf[2][4];
#pragma unroll
            for (int p = 0; p < 2; p++) {
                int n = wn * 32 + p * 16 + bRowO;
                ldsm4(bf[p][0], bf[p][1], bf[p][2], bf[p][3],
                      bBase + (n * GP + kc + bColO) * 4);
            }
#pragma unroll
            for (int i = 0; i < 4; i++)
#pragma unroll
                for (int j = 0; j < 4; j++)
                    mma_tf32(acc[i][j], a[i],
                             bf[j >> 1][(j & 1) * 2], bf[j >> 1][(j & 1) * 2 + 1]);
        }
        if (kt + 2 < GM_KT) GM_LOAD(kt + 2);
    }

    // ---- epilogue: bias add + scatter to [B,H,T,hs] ----
    const int g  = lane >> 2;
    const int t2 = (lane & 3) * 2;
#pragma unroll
    for (int i = 0; i < 4; i++) {
        int m    = row0 + wm * 64 + i * 16 + g;
        int bidx = m >> 11;
        int ti   = m & (T_ - 1);
#pragma unroll
        for (int j = 0; j < 4; j++) {
            int n  = col0 + wn * 32 + j * 8 + t2;
            int sQ = n >> 10;
            int h  = (n >> 6) & (H_ - 1);
            int d  = n & (HS_ - 1);
            float b0 = __ldg(bias + n), b1 = __ldg(bias + n + 1);
            float* dst = (sQ == 0) ? g_q : ((sQ == 1) ? g_k : g_v);
            float* p0  = dst + (((size_t)bidx * H_ + h) * T_ + ti) * HS_ + d;
            *(float2*)p0 = make_float2(acc[i][j][0] + b0, acc[i][j][1] + b1);
            *(float2*)(p0 + 8 * HS_) =
                make_float2(acc[i][j][2] + b0, acc[i][j][3] + b1);
        }
    }
}

// ---------------------------------------------------------------------------
// Kernel 2: causal flash attention on tf32 mma.sync.
// Br=128, Bc=64, 128 threads (4 warps x 32 q-rows). Pitch-68 smem.
// ---------------------------------------------------------------------------
#define AP 68
#define FA_Q0 0
#define FA_K0 (128 * AP)            // 8704
#define FA_V0 (FA_K0 + 64 * AP)     // 13056
#define FA_P0 (FA_V0 + 64 * AP)     // 17408
#define FA_SMEM_BYTES ((FA_P0 + 128 * AP) * 4)   // 104448 B

__global__ __launch_bounds__(128)
void flash_tc(float* __restrict__ out) {
    extern __shared__ float sm[];
    float* Qs = sm + FA_Q0;
    float* Ks = sm + FA_K0;
    float* Vt = sm + FA_V0;   // transposed: Vt[d][key]
    float* Ps = sm + FA_P0;

    const int tid  = threadIdx.x;
    const int lane = tid & 31;
    const int w    = tid >> 5;
    const int bh   = blockIdx.y;
    const int b    = bh >> 4;
    const int h    = bh & (H_ - 1);
    const int qt   = gridDim.x - 1 - blockIdx.x;   // biggest first
    const int q0   = qt * 128;
    const size_t base = (size_t)bh * T_ * HS_;

    // Load Q (scale folded, tf32-rounded)
#pragma unroll
    for (int p = 0; p < 16; p++) {
        int idx = tid + p * 128;
        int r = idx >> 4, c = (idx & 15) * 4;
        float4 v = *(const float4*)(g_q + base + (size_t)(q0 + r) * HS_ + c);
        v.x = to_tf32(v.x * 0.125f); v.y = to_tf32(v.y * 0.125f);
        v.z = to_tf32(v.z * 0.125f); v.w = to_tf32(v.w * 0.125f);
        *(float4*)&Qs[r * AP + c] = v;
    }

    float o[2][8][4];
    float m_[2][2], l_[2][2];
#pragma unroll
    for (int i = 0; i < 2; i++) {
        m_[i][0] = m_[i][1] = -1e30f;
        l_[i][0] = l_[i][1] = 0.0f;
#pragma unroll
        for (int j = 0; j < 8; j++)
#pragma unroll
            for (int e = 0; e < 4; e++) o[i][j][e] = 0.0f;
    }

    const uint32_t qBase = smem_u32(Qs);
    const uint32_t kBase = smem_u32(Ks);
    const uint32_t vBase = smem_u32(Vt);
    const uint32_t pBase = smem_u32(Ps);

    const int aRow  = lane & 15;
    const int aCol  = (lane >> 4) * 4;
    const int bRowO = ((lane & 16) ? 8 : 0) + (lane & 7);
    const int bColO = (lane & 8) ? 4 : 0;
    const int g  = lane >> 2;
    const int t2 = (lane & 3) * 2;

    const int nkt = 2 * qt + 2;
    for (int kt = 0; kt < nkt; kt++) {
        const int k0 = kt * 64;
        __syncthreads();   // prior iter done reading Ks/Vt (iter0: Qs ready)

        // K tile verbatim (rounded)
#pragma unroll
        for (int p = 0; p < 8; p++) {
            int idx = tid + p * 128;
            int r = idx >> 4, c = (idx & 15) * 4;
            float4 v = *(const float4*)(g_k + base + (size_t)(k0 + r) * HS_ + c);
            v.x = to_tf32(v.x); v.y = to_tf32(v.y);
            v.z = to_tf32(v.z); v.w = to_tf32(v.w);
            *(float4*)&Ks[r * AP + c] = v;
        }
        // V tile transposed in 4x4 blocks (conflict-free mapping)
#pragma unroll
        for (int p = 0; p < 2; p++) {
            int db = ((lane >> 3) + ((w & 1) << 2) + (p << 3)) * 4;  // 0..60
            int kb = ((lane & 7) + ((w >> 1) << 3)) * 4;             // 0..60
            const float* vp = g_v + base + (size_t)(k0 + kb) * HS_ + db;
            float4 r0 = *(const float4*)(vp);
            float4 r1 = *(const float4*)(vp + HS_);
            float4 r2 = *(const float4*)(vp + 2 * HS_);
            float4 r3 = *(const float4*)(vp + 3 * HS_);
            *(float4*)&Vt[(db + 0) * AP + kb] = make_float4(
                to_tf32(r0.x), to_tf32(r1.x), to_tf32(r2.x), to_tf32(r3.x));
            *(float4*)&Vt[(db + 1) * AP + kb] = make_float4(
                to_tf32(r0.y), to_tf32(r1.y), to_tf32(r2.y), to_tf32(r3.y));
            *(float4*)&Vt[(db + 2) * AP + kb] = make_float4(
                to_tf32(r0.z), to_tf32(r1.z), to_tf32(r2.z), to_tf32(r3.z));
            *(float4*)&Vt[(db + 3) * AP + kb] = make_float4(
                to_tf32(r0.w), to_tf32(r1.w), to_tf32(r2.w), to_tf32(r3.w));
        }
        __syncthreads();

        // S = Q K^T
        float s[2][8][4];
#pragma unroll
        for (int i = 0; i < 2; i++)
#pragma unroll
            for (int j = 0; j < 8; j++)
#pragma unroll
                for (int e = 0; e < 4; e++) s[i][j][e] = 0.0f;

#pragma unroll
        for (int ks = 0; ks < 8; ks++) {
            const int kc = ks * 8;
            uint32_t a[2][4];
#pragma unroll
            for (int i = 0; i < 2; i++) {
                int row = w * 32 + i * 16 + aRow;
                ldsm4(a[i][0], a[i][1], a[i][2], a[i][3],
                      qBase + (row * AP + kc + aCol) * 4);
            }
            uint32_t bf[4][4];
#pragma unroll
            for (int p = 0; p < 4; p++) {
                int key = p * 16 + bRowO;
                ldsm4(bf[p][0], bf[p][1], bf[p][2], bf[p][3],
                      kBase + (key * AP + kc + bColO) * 4);
            }
#pragma unroll
            for (int i = 0; i < 2; i++)
#pragma unroll
                for (int j = 0; j < 8; j++)
                    mma_tf32(s[i][j], a[i],
                             bf[j >> 1][(j & 1) * 2], bf[j >> 1][(j & 1) * 2 + 1]);
        }

        // causal mask (only the two diagonal tiles need it)
        if (kt >= 2 * qt) {
#pragma unroll
            for (int i = 0; i < 2; i++)
#pragma unroll
                for (int j = 0; j < 8; j++)
#pragma unroll
                    for (int e = 0; e < 4; e++) {
                        int rg = q0 + w * 32 + i * 16 + g + ((e & 2) ? 8 : 0);
                        int kg = k0 + j * 8 + t2 + (e & 1);
                        if (kg > rg) s[i][j][e] = -1e30f;
                    }
        }

        // online softmax (rows owned by 4-lane groups; xor over lane bits 0-1)
#pragma unroll
        for (int i = 0; i < 2; i++) {
#pragma unroll
            for (int hf = 0; hf < 2; hf++) {
                const int e0 = hf * 2;
                float mx = -1e30f;
#pragma unroll
                for (int j = 0; j < 8; j++)
                    mx = fmaxf(mx, fmaxf(s[i][j][e0], s[i][j][e0 + 1]));
                mx = fmaxf(mx, __shfl_xor_sync(0xffffffffu, mx, 1));
                mx = fmaxf(mx, __shfl_xor_sync(0xffffffffu, mx, 2));
                float nm = fmaxf(m_[i][hf], mx);
                float sum = 0.0f;
#pragma unroll
                for (int j = 0; j < 8; j++) {
                    s[i][j][e0]     = __expf(s[i][j][e0] - nm);
                    s[i][j][e0 + 1] = __expf(s[i][j][e0 + 1] - nm);
                    sum += s[i][j][e0] + s[i][j][e0 + 1];
                }
                sum += __shfl_xor_sync(0xffffffffu, sum, 1);
                sum += __shfl_xor_sync(0xffffffffu, sum, 2);
                float al = __expf(m_[i][hf] - nm);
                l_[i][hf] = l_[i][hf] * al + sum;
                m_[i][hf] = nm;
#pragma unroll
                for (int j = 0; j < 8; j++) {
                    o[i][j][e0]     *= al;
                    o[i][j][e0 + 1] *= al;
                }
            }
        }

        // stage P (tf32-rounded); rows are warp-private
#pragma unroll
        for (int i = 0; i < 2; i++) {
            int row = w * 32 + i * 16 + g;
#pragma unroll
            for (int j = 0; j < 8; j++) {
                *(float2*)&Ps[row * AP + j * 8 + t2] =
                    make_float2(to_tf32(s[i][j][0]), to_tf32(s[i][j][1]));
                *(float2*)&Ps[(row + 8) * AP + j * 8 + t2] =
                    make_float2(to_tf32(s[i][j][2]), to_tf32(s[i][j][3]));
            }
        }
        __syncwarp();

        // O += P V
#pragma unroll
        for (int ks = 0; ks < 8; ks++) {
            const int kc = ks * 8;
            uint32_t a[2][4];
#pragma unroll
            for (int i = 0; i < 2; i++) {
                int row = w * 32 + i * 16 + aRow;
                ldsm4(a[i][0], a[i][1], a[i][2], a[i][3],
                      pBase + (row * AP + kc + aCol) * 4);
            }
            uint32_t bf[4][4];
#pragma unroll
            for (int p = 0; p < 4; p++) {
                int d = p * 16 + bRowO;
                ldsm4(bf[p][0], bf[p][1], bf[p][2], bf[p][3],
                      vBase + (d * AP + kc + bColO) * 4);
            }
#pragma unroll
            for (int i = 0; i < 2; i++)
#pragma unroll
                for (int j = 0; j < 8; j++)
                    mma_tf32(o[i][j], a[i],
                             bf[j >> 1][(j & 1) * 2], bf[j >> 1][(j & 1) * 2 + 1]);
        }
    }

    // finalize + write out[b, t, h*64 + d]
#pragma unroll
    for (int i = 0; i < 2; i++) {
        float inv0 = 1.0f / l_[i][0];
        float inv1 = 1.0f / l_[i][1];
        int row = q0 + w * 32 + i * 16 + g;
#pragma unroll
        for (int j = 0; j < 8; j++) {
            int d = j * 8 + t2;
            float* p0 = out + (size_t)(b * T_ + row) * C_ + h * HS_ + d;
            *(float2*)p0 = make_float2(o[i][j][0] * inv0, o[i][j][1] * inv0);
            *(float2*)(p0 + 8 * C_) =
                make_float2(o[i][j][2] * inv1, o[i][j][3] * inv1);
        }
    }
}

// ---------------------------------------------------------------------------
extern "C" void kernel_launch(void* const* d_in, const int* in_sizes, int n_in,
                              void* d_out, int out_size) {
    const float* x    = (const float*)d_in[0];
    const float* W    = (const float*)d_in[1];
    const float* bias = (const float*)d_in[2];
    float* out = (float*)d_out;

    cudaFuncSetAttribute(qkv_gemm_tc,
                         cudaFuncAttributeMaxDynamicSharedMemorySize,
                         GM_SMEM_BYTES);
    cudaFuncSetAttribute(flash_tc,
                         cudaFuncAttributeMaxDynamicSharedMemorySize,
                         FA_SMEM_BYTES);

    round_inputs<<<(NX4 + NW4) / 256, 256>>>(x, W);

    dim3 g1(N3_ / 128, M_ / 128);           // 24 x 64
    qkv_gemm_tc<<<g1, 256, GM_SMEM_BYTES>>>(bias);

    dim3 g2(T_ / 128, B_ * H_);             // 16 x 64
    flash_tc<<<g2, 128, FA_SMEM_BYTES>>>(out);
}

// round 4
// speedup vs baseline: 3.6283x; 1.0009x over previous
#include <cuda_runtime.h>
#include <cstdint>

// Problem constants (fixed: B=4, T=2048, C=1024, H=16)
#define B_  4
#define T_  2048
#define C_  1024
#define H_  16
#define HS_ 64
#define M_  (B_ * T_)     // 8192
#define N3_ (3 * C_)      // 3072
#define K_  C_            // 1024

// Scratch (__device__ globals).
// g_q, g_k: [B,H,T,hs], tf32-rounded (q pre-scaled by 0.125).
// g_vt:     [B,H,hs,T], tf32-rounded, TRANSPOSED for direct ldmatrix B-frags.
__device__ float g_q [(size_t)B_ * H_ * T_ * HS_];
__device__ float g_k [(size_t)B_ * H_ * T_ * HS_];
__device__ float g_vt[(size_t)B_ * H_ * HS_ * T_];

// ---------------------------------------------------------------------------
__device__ __forceinline__ uint32_t smem_u32(const void* p) {
    uint32_t a;
    asm("{ .reg .u64 t; cvta.to.shared.u64 t, %1; cvt.u32.u64 %0, t; }"
        : "=r"(a) : "l"(p));
    return a;
}
__device__ __forceinline__ float to_tf32(float x) {
    uint32_t u;
    asm("cvt.rna.tf32.f32 %0, %1;" : "=r"(u) : "f"(x));
    return __uint_as_float(u);
}
__device__ __forceinline__ uint32_t rnd_u32(uint32_t u) {
    return __float_as_uint(to_tf32(__uint_as_float(u)));
}
__device__ __forceinline__ void ldsm4(uint32_t& r0, uint32_t& r1,
                                      uint32_t& r2, uint32_t& r3, uint32_t addr) {
    asm volatile("ldmatrix.sync.aligned.m8n8.x4.shared.b16 {%0,%1,%2,%3}, [%4];"
                 : "=r"(r0), "=r"(r1), "=r"(r2), "=r"(r3) : "r"(addr));
}
__device__ __forceinline__ void mma_tf32(float* c, const uint32_t* a,
                                         uint32_t b0, uint32_t b1) {
    asm volatile(
        "mma.sync.aligned.m16n8k8.row.col.f32.tf32.tf32.f32 "
        "{%0,%1,%2,%3}, {%4,%5,%6,%7}, {%8,%9}, {%0,%1,%2,%3};"
        : "+f"(c[0]), "+f"(c[1]), "+f"(c[2]), "+f"(c[3])
        : "r"(a[0]), "r"(a[1]), "r"(a[2]), "r"(a[3]), "r"(b0), "r"(b1));
}
__device__ __forceinline__ void cp16(uint32_t dst_smem, const void* src) {
    asm volatile("cp.async.cg.shared.global [%0], [%1], 16;"
                 :: "r"(dst_smem), "l"(src));
}

// ---------------------------------------------------------------------------
// Kernel 1: QKV GEMM, tf32 mma.sync.  D[m,n] = sum_k x[m,k]*W[n,k] + b[n]
// CTA 128x256, BK=32, 8 warps (2x4, each 64x64), 3-stage cp.async, pitch 36.
// Epilogue rounds q/k/v to tf32, scales q by 0.125, transposes v.
// ---------------------------------------------------------------------------
#define GP 36
#define GM_STAGE_FLT ((128 + 256) * GP)            // 13824 floats
#define GM_SMEM_BYTES (3 * GM_STAGE_FLT * 4)       // 165888 B
#define GM_KT (K_ / 32)                            // 32

__global__ __launch_bounds__(256, 1)
void qkv_gemm_tc(const float* __restrict__ x,
                 const float* __restrict__ Wm,
                 const float* __restrict__ bias) {
    extern __shared__ float sm[];
    const int tid  = threadIdx.x;
    const int lane = tid & 31;
    const int w    = tid >> 5;
    const int wm   = w >> 2;                 // 0..1  (64-row block)
    const int wn   = w & 3;                  // 0..3  (64-col block)
    const int row0 = blockIdx.y * 128;
    const int col0 = blockIdx.x * 256;

    float acc[4][8][4];
#pragma unroll
    for (int i = 0; i < 4; i++)
#pragma unroll
        for (int j = 0; j < 8; j++)
#pragma unroll
            for (int e = 0; e < 4; e++) acc[i][j][e] = 0.0f;

    const int lr = tid >> 3;                 // 0..31
    const int lc = (tid & 7) * 4;            // 0..28
#define GM_LOAD(kt) do {                                                       \
    int s_ = (kt) % 3;                                                         \
    uint32_t aOff_ = smem_u32(sm + s_ * GM_STAGE_FLT);                         \
    uint32_t bOff_ = aOff_ + 128 * GP * 4;                                     \
    const float* Ab_ = x  + (size_t)row0 * K_ + (kt) * 32;                     \
    const float* Bb_ = Wm + (size_t)col0 * K_ + (kt) * 32;                     \
    _Pragma("unroll")                                                          \
    for (int q_ = 0; q_ < 4; q_++) {                                           \
        int r_ = lr + q_ * 32;                                                 \
        cp16(aOff_ + (r_ * GP + lc) * 4, Ab_ + (size_t)r_ * K_ + lc);          \
    }                                                                          \
    _Pragma("unroll")                                                          \
    for (int q_ = 0; q_ < 8; q_++) {                                           \
        int r_ = lr + q_ * 32;                                                 \
        cp16(bOff_ + (r_ * GP + lc) * 4, Bb_ + (size_t)r_ * K_ + lc);          \
    }                                                                          \
    asm volatile("cp.async.commit_group;" ::: "memory");                       \
} while (0)

    GM_LOAD(0);
    GM_LOAD(1);

    const int aRow  = lane & 15;
    const int aCol  = (lane >> 4) * 4;
    const int bRowO = ((lane & 16) ? 8 : 0) + (lane & 7);
    const int bColO = (lane & 8) ? 4 : 0;

    for (int kt = 0; kt < GM_KT; kt++) {
        if (kt + 1 < GM_KT) asm volatile("cp.async.wait_group 1;" ::: "memory");
        else                asm volatile("cp.async.wait_group 0;" ::: "memory");
        __syncthreads();

        const uint32_t aBase = smem_u32(sm + (kt % 3) * GM_STAGE_FLT);
        const uint32_t bBase = aBase + 128 * GP * 4;

#pragma unroll
        for (int ks = 0; ks < 4; ks++) {
            const int kc = ks * 8;
            uint32_t a[4][4];
#pragma unroll
            for (int i = 0; i < 4; i++) {
                int row = wm * 64 + i * 16 + aRow;
                ldsm4(a[i][0], a[i][1], a[i][2], a[i][3],
                      aBase + (row * GP + kc + aCol) * 4);
#pragma unroll
                for (int r = 0; r < 4; r++) a[i][r] = rnd_u32(a[i][r]);
            }
            uint32_t bf[4][4];
#pragma unroll
            for (int p = 0; p < 4; p++) {
                int n = wn * 64 + p * 16 + bRowO;
                ldsm4(bf[p][0], bf[p][1], bf[p][2], bf[p][3],
                      bBase + (n * GP + kc + bColO) * 4);
#pragma unroll
                for (int r = 0; r < 4; r++) bf[p][r] = rnd_u32(bf[p][r]);
            }
#pragma unroll
            for (int i = 0; i < 4; i++)
#pragma unroll
                for (int j = 0; j < 8; j++)
                    mma_tf32(acc[i][j], a[i],
                             bf[j >> 1][(j & 1) * 2], bf[j >> 1][(j & 1) * 2 + 1]);
        }
        if (kt + 2 < GM_KT) GM_LOAD(kt + 2);
    }

    // ---- epilogue: bias, tf32 round, scatter (s constant per CTA) ----
    const int g  = lane >> 2;
    const int t2 = (lane & 3) * 2;
    const int sQ = col0 >> 10;                        // 0:q 1:k 2:v
    const int h  = ((col0 + wn * 64) >> 6) & (H_ - 1);

    float rb[8][2];
#pragma unroll
    for (int j = 0; j < 8; j++) {
        rb[j][0] = __ldg(bias + col0 + wn * 64 + j * 8 + t2);
        rb[j][1] = __ldg(bias + col0 + wn * 64 + j * 8 + t2 + 1);
    }

#pragma unroll
    for (int i = 0; i < 4; i++) {
        int m    = row0 + wm * 64 + i * 16 + g;
        int bidx = m >> 11;
        int ti   = m & (T_ - 1);
#pragma unroll
        for (int j = 0; j < 8; j++) {
            int d = j * 8 + t2;
            float c0 = acc[i][j][0] + rb[j][0];
            float c1 = acc[i][j][1] + rb[j][1];
            float c2 = acc[i][j][2] + rb[j][0];
            float c3 = acc[i][j][3] + rb[j][1];
            if (sQ == 0) {
                c0 *= 0.125f; c1 *= 0.125f; c2 *= 0.125f; c3 *= 0.125f;
            }
            c0 = to_tf32(c0); c1 = to_tf32(c1);
            c2 = to_tf32(c2); c3 = to_tf32(c3);
            if (sQ == 2) {
                float* p = g_vt + (((size_t)bidx * H_ + h) * HS_ + d) * T_ + ti;
                p[0]        = c0;  p[T_]         = c1;
                p[8]        = c2;  p[T_ + 8]     = c3;
            } else {
                float* dst = (sQ == 0) ? g_q : g_k;
                float* p = dst + (((size_t)bidx * H_ + h) * T_ + ti) * HS_ + d;
                *(float2*)p            = make_float2(c0, c1);
                *(float2*)(p + 8 * HS_) = make_float2(c2, c3);
            }
        }
    }
}

// ---------------------------------------------------------------------------
// Kernel 2: causal flash attention, tf32 mma.sync, all operands pre-rounded.
// Br=128 (8 warps x 16 rows), Bc=64, single-buffer K/Vt via cp.async,
// 2 CTAs/SM. Pitch 68.
// ---------------------------------------------------------------------------
#define AP 68
#define FQ 0
#define FK (128 * AP)              // 8704
#define FV (FK + 64 * AP)          // 13056
#define FP (FV + 64 * AP)          // 17408
#define FA_SMEM_BYTES ((FP + 128 * AP) * 4)   // 104448 B

__global__ __launch_bounds__(256, 2)
void flash_tc(float* __restrict__ out) {
    extern __shared__ float sm[];
    const int tid  = threadIdx.x;
    const int lane = tid & 31;
    const int w    = tid >> 5;
    const int bh   = blockIdx.y;
    const int b    = bh >> 4;
    const int h    = bh & (H_ - 1);
    const int qt   = gridDim.x - 1 - blockIdx.x;   // biggest first
    const int q0   = qt * 128;
    const size_t base  = (size_t)bh * T_ * HS_;    // q/k
    const size_t baseV = (size_t)bh * HS_ * T_;    // vt

    const uint32_t qB = smem_u32(sm + FQ);
    const uint32_t kB = smem_u32(sm + FK);
    const uint32_t vB = smem_u32(sm + FV);
    const uint32_t pB = smem_u32(sm + FP);

    const int lr = tid >> 4;                 // 0..15
    const int lc = (tid & 15) * 4;           // 0..60

    // Prologue: stage Q (128x64) + K(0) + Vt(0), one commit group.
#pragma unroll
    for (int p = 0; p < 8; p++) {
        int r = lr + p * 16;
        cp16(qB + (r * AP + lc) * 4, g_q + base + (size_t)(q0 + r) * HS_ + lc);
    }
#pragma unroll
    for (int p = 0; p < 4; p++) {
        int r = lr + p * 16;
        cp16(kB + (r * AP + lc) * 4, g_k + base + (size_t)r * HS_ + lc);
        cp16(vB + (r * AP + lc) * 4, g_vt + baseV + (size_t)r * T_ + lc);
    }
    asm volatile("cp.async.commit_group;" ::: "memory");

    float o[8][4];
    float m_[2], l_[2];
    m_[0] = m_[1] = -1e30f;
    l_[0] = l_[1] = 0.0f;
#pragma unroll
    for (int j = 0; j < 8; j++)
#pragma unroll
        for (int e = 0; e < 4; e++) o[j][e] = 0.0f;

    const int aRow  = lane & 15;
    const int aCol  = (lane >> 4) * 4;
    const int bRowO = ((lane & 16) ? 8 : 0) + (lane & 7);
    const int bColO = (lane & 8) ? 4 : 0;
    const int g  = lane >> 2;
    const int t2 = (lane & 3) * 2;

    const int nkt = 2 * qt + 2;
    for (int kt = 0; kt < nkt; kt++) {
        const int k0 = kt * 64;
        asm volatile("cp.async.wait_group 0;" ::: "memory");
        __syncthreads();

        // S = Q K^T   (rows w*16..w*16+15)
        float s[8][4];
#pragma unroll
        for (int j = 0; j < 8; j++)
#pragma unroll
            for (int e = 0; e < 4; e++) s[j][e] = 0.0f;

#pragma unroll
        for (int ks = 0; ks < 8; ks++) {
            const int kc = ks * 8;
            uint32_t a[4];
            ldsm4(a[0], a[1], a[2], a[3],
                  qB + ((w * 16 + aRow) * AP + kc + aCol) * 4);
            uint32_t bf[4][4];
#pragma unroll
            for (int p = 0; p < 4; p++)
                ldsm4(bf[p][0], bf[p][1], bf[p][2], bf[p][3],
                      kB + ((p * 16 + bRowO) * AP + kc + bColO) * 4);
#pragma unroll
            for (int j = 0; j < 8; j++)
                mma_tf32(s[j], a,
                         bf[j >> 1][(j & 1) * 2], bf[j >> 1][(j & 1) * 2 + 1]);
        }

        // causal mask (two diagonal tiles only)
        if (kt >= 2 * qt) {
#pragma unroll
            for (int j = 0; j < 8; j++)
#pragma unroll
                for (int e = 0; e < 4; e++) {
                    int rg = q0 + w * 16 + g + ((e & 2) ? 8 : 0);
                    int kg = k0 + j * 8 + t2 + (e & 1);
                    if (kg > rg) s[j][e] = -1e30f;
                }
        }

        // online softmax (4-lane row groups)
#pragma unroll
        for (int hf = 0; hf < 2; hf++) {
            const int e0 = hf * 2;
            float mx = -1e30f;
#pragma unroll
            for (int j = 0; j < 8; j++)
                mx = fmaxf(mx, fmaxf(s[j][e0], s[j][e0 + 1]));
            mx = fmaxf(mx, __shfl_xor_sync(0xffffffffu, mx, 1));
            mx = fmaxf(mx, __shfl_xor_sync(0xffffffffu, mx, 2));
            float nm = fmaxf(m_[hf], mx);
            float sum = 0.0f;
#pragma unroll
            for (int j = 0; j < 8; j++) {
                s[j][e0]     = __expf(s[j][e0] - nm);
                s[j][e0 + 1] = __expf(s[j][e0 + 1] - nm);
                sum += s[j][e0] + s[j][e0 + 1];
            }
            sum += __shfl_xor_sync(0xffffffffu, sum, 1);
            sum += __shfl_xor_sync(0xffffffffu, sum, 2);
            float al = __expf(m_[hf] - nm);
            l_[hf] = l_[hf] * al + sum;
            m_[hf] = nm;
#pragma unroll
            for (int j = 0; j < 8; j++) {
                o[j][e0]     *= al;
                o[j][e0 + 1] *= al;
            }
        }

        // stage P (tf32-rounded; rows warp-private)
        {
            int row = w * 16 + g;
#pragma unroll
            for (int j = 0; j < 8; j++) {
                *(float2*)&sm[FP + row * AP + j * 8 + t2] =
                    make_float2(to_tf32(s[j][0]), to_tf32(s[j][1]));
                *(float2*)&sm[FP + (row + 8) * AP + j * 8 + t2] =
                    make_float2(to_tf32(s[j][2]), to_tf32(s[j][3]));
            }
        }
        __syncwarp();

        // O += P V    (B-frags straight from transposed Vt)
#pragma unroll
        for (int ks = 0; ks < 8; ks++) {
            const int kc = ks * 8;
            uint32_t a[4];
            ldsm4(a[0], a[1], a[2], a[3],
                  pB + ((w * 16 + aRow) * AP + kc + aCol) * 4);
            uint32_t bf[4][4];
#pragma unroll
            for (int p = 0; p < 4; p++)
                ldsm4(bf[p][0], bf[p][1], bf[p][2], bf[p][3],
                      vB + ((p * 16 + bRowO) * AP + kc + bColO) * 4);
#pragma unroll
            for (int j = 0; j < 8; j++)
                mma_tf32(o[j], a,
                         bf[j >> 1][(j & 1) * 2], bf[j >> 1][(j & 1) * 2 + 1]);
        }

        __syncthreads();     // everyone done reading K/Vt
        if (kt + 1 < nkt) {
            const int kn = k0 + 64;
#pragma unroll
            for (int p = 0; p < 4; p++) {
                int r = lr + p * 16;
                cp16(kB + (r * AP + lc) * 4,
                     g_k + base + (size_t)(kn + r) * HS_ + lc);
                cp16(vB + (r * AP + lc) * 4,
                     g_vt + baseV + (size_t)r * T_ + kn + lc);
            }
        }
        asm volatile("cp.async.commit_group;" ::: "memory");
    }

    // finalize + write out[b, t, h*64 + d]
    float inv0 = 1.0f / l_[0];
    float inv1 = 1.0f / l_[1];
    int row = q0 + w * 16 + g;
#pragma unroll
    for (int j = 0; j < 8; j++) {
        int d = j * 8 + t2;
        float* p0 = out + (size_t)(b * T_ + row) * C_ + h * HS_ + d;
        *(float2*)p0           = make_float2(o[j][0] * inv0, o[j][1] * inv0);
        *(float2*)(p0 + 8 * C_) = make_float2(o[j][2] * inv1, o[j][3] * inv1);
    }
}

// ---------------------------------------------------------------------------
extern "C" void kernel_launch(void* const* d_in, const int* in_sizes, int n_in,
                              void* d_out, int out_size) {
    const float* x    = (const float*)d_in[0];
    const float* W    = (const float*)d_in[1];
    const float* bias = (const float*)d_in[2];
    float* out = (float*)d_out;

    cudaFuncSetAttribute(qkv_gemm_tc,
                         cudaFuncAttributeMaxDynamicSharedMemorySize,
                         GM_SMEM_BYTES);
    cudaFuncSetAttribute(flash_tc,
                         cudaFuncAttributeMaxDynamicSharedMemorySize,
                         FA_SMEM_BYTES);

    dim3 g1(N3_ / 256, M_ / 128);           // 12 x 64 = 768 CTAs
    qkv_gemm_tc<<<g1, 256, GM_SMEM_BYTES>>>(x, W, bias);

    dim3 g2(T_ / 128, B_ * H_);             // 16 x 64 = 1024 CTAs
    flash_tc<<<g2, 256, FA_SMEM_BYTES>>>(out);
}

// round 5
// speedup vs baseline: 4.3030x; 1.1860x over previous
#include <cuda_runtime.h>
#include <cstdint>

// Problem constants (fixed: B=4, T=2048, C=1024, H=16)
#define B_  4
#define T_  2048
#define C_  1024
#define H_  16
#define HS_ 64
#define M_  (B_ * T_)     // 8192
#define N3_ (3 * C_)      // 3072
#define K_  C_            // 1024

// Scratch (__device__ globals).
__device__ float g_q [(size_t)B_ * H_ * T_ * HS_];   // tf32, pre-scaled 0.125
__device__ float g_k [(size_t)B_ * H_ * T_ * HS_];   // tf32
__device__ float g_vt[(size_t)B_ * H_ * HS_ * T_];   // tf32, transposed [d][t]
__device__ float g_xr[(size_t)M_ * K_];              // tf32-rounded x
__device__ float g_wr[(size_t)N3_ * K_];             // tf32-rounded W

// ---------------------------------------------------------------------------
__device__ __forceinline__ uint32_t smem_u32(const void* p) {
    uint32_t a;
    asm("{ .reg .u64 t; cvta.to.shared.u64 t, %1; cvt.u32.u64 %0, t; }"
        : "=r"(a) : "l"(p));
    return a;
}
__device__ __forceinline__ float to_tf32(float x) {
    uint32_t u;
    asm("cvt.rna.tf32.f32 %0, %1;" : "=r"(u) : "f"(x));
    return __uint_as_float(u);
}
__device__ __forceinline__ void ldsm4(uint32_t& r0, uint32_t& r1,
                                      uint32_t& r2, uint32_t& r3, uint32_t addr) {
    asm volatile("ldmatrix.sync.aligned.m8n8.x4.shared.b16 {%0,%1,%2,%3}, [%4];"
                 : "=r"(r0), "=r"(r1), "=r"(r2), "=r"(r3) : "r"(addr));
}
__device__ __forceinline__ void mma_tf32(float* c, const uint32_t* a,
                                         uint32_t b0, uint32_t b1) {
    asm volatile(
        "mma.sync.aligned.m16n8k8.row.col.f32.tf32.tf32.f32 "
        "{%0,%1,%2,%3}, {%4,%5,%6,%7}, {%8,%9}, {%0,%1,%2,%3};"
        : "+f"(c[0]), "+f"(c[1]), "+f"(c[2]), "+f"(c[3])
        : "r"(a[0]), "r"(a[1]), "r"(a[2]), "r"(a[3]), "r"(b0), "r"(b1));
}
__device__ __forceinline__ void mma_tf32u(uint32_t* c_is_f, const uint32_t* a,
                                          uint32_t b0, uint32_t b1) {
    mma_tf32((float*)c_is_f, a, b0, b1);
}
__device__ __forceinline__ void cp16(uint32_t dst_smem, const void* src) {
    asm volatile("cp.async.cg.shared.global [%0], [%1], 16;"
                 :: "r"(dst_smem), "l"(src));
}
// Swizzled byte offsets (XOR bank-quad with row%8). Rows 128B / 256B.
__device__ __forceinline__ uint32_t sw128(int row, int colf) {
    return (uint32_t)(row * 128 + colf * 4) ^ (uint32_t)((row & 7) << 4);
}
__device__ __forceinline__ uint32_t sw256(int row, int colf) {
    return (uint32_t)(row * 256 + colf * 4) ^ (uint32_t)((row & 7) << 4);
}

// ---------------------------------------------------------------------------
// Kernel 0: round x and W to tf32 scratch.
// ---------------------------------------------------------------------------
#define NX4 (M_ * K_ / 4)
#define NW4 (N3_ * K_ / 4)

__global__ __launch_bounds__(256)
void round_inputs(const float* __restrict__ x, const float* __restrict__ W) {
    int i = blockIdx.x * 256 + threadIdx.x;
    if (i < NX4) {
        float4 v = ((const float4*)x)[i];
        v.x = to_tf32(v.x); v.y = to_tf32(v.y);
        v.z = to_tf32(v.z); v.w = to_tf32(v.w);
        ((float4*)g_xr)[i] = v;
    } else {
        int j = i - NX4;
        float4 v = ((const float4*)W)[j];
        v.x = to_tf32(v.x); v.y = to_tf32(v.y);
        v.z = to_tf32(v.z); v.w = to_tf32(v.w);
        ((float4*)g_wr)[j] = v;
    }
}

// ---------------------------------------------------------------------------
// Kernel 1: QKV GEMM, tf32 mma.sync.  CTA 128x128, BK=32, 8 warps (2x4),
// 3-stage cp.async, swizzled pitch-32 smem (96KB) -> 2 CTAs/SM.
// ---------------------------------------------------------------------------
#define GM_STAGE_B 32768                     // (128+128)*32*4
#define GM_SMEM_BYTES (3 * GM_STAGE_B)       // 98304
#define GM_KT (K_ / 32)                      // 32

__global__ __launch_bounds__(256, 2)
void qkv_gemm_tc(const float* __restrict__ bias) {
    extern __shared__ float sm[];
    const uint32_t sb = smem_u32(sm);
    const int tid  = threadIdx.x;
    const int lane = tid & 31;
    const int w    = tid >> 5;
    const int wm   = w >> 2;                 // 0..1 (64-row block)
    const int wn   = w & 3;                  // 0..3 (32-col block)
    const int row0 = blockIdx.y * 128;
    const int col0 = blockIdx.x * 128;

    float acc[4][4][4];
#pragma unroll
    for (int i = 0; i < 4; i++)
#pragma unroll
        for (int j = 0; j < 4; j++)
#pragma unroll
            for (int e = 0; e < 4; e++) acc[i][j][e] = 0.0f;

    const int lr = tid >> 3;                 // 0..31
    const int lc = (tid & 7) * 4;            // 0..28
#define GM_LOAD(kt) do {                                                       \
    uint32_t aOff_ = sb + ((kt) % 3) * GM_STAGE_B;                             \
    uint32_t bOff_ = aOff_ + 16384;                                            \
    const float* Ab_ = g_xr + (size_t)row0 * K_ + (kt) * 32;                   \
    const float* Bb_ = g_wr + (size_t)col0 * K_ + (kt) * 32;                   \
    _Pragma("unroll")                                                          \
    for (int q_ = 0; q_ < 4; q_++) {                                           \
        int r_ = lr + q_ * 32;                                                 \
        cp16(aOff_ + sw128(r_, lc), Ab_ + (size_t)r_ * K_ + lc);               \
        cp16(bOff_ + sw128(r_, lc), Bb_ + (size_t)r_ * K_ + lc);               \
    }                                                                          \
    asm volatile("cp.async.commit_group;" ::: "memory");                       \
} while (0)

    GM_LOAD(0);
    GM_LOAD(1);

    const int aRow  = lane & 15;
    const int aCol  = (lane >> 4) * 4;
    const int bRowO = ((lane & 16) ? 8 : 0) + (lane & 7);
    const int bColO = (lane & 8) ? 4 : 0;

    for (int kt = 0; kt < GM_KT; kt++) {
        if (kt + 1 < GM_KT) asm volatile("cp.async.wait_group 1;" ::: "memory");
        else                asm volatile("cp.async.wait_group 0;" ::: "memory");
        __syncthreads();

        const uint32_t aBase = sb + (kt % 3) * GM_STAGE_B;
        const uint32_t bBase = aBase + 16384;

#pragma unroll
        for (int ks = 0; ks < 4; ks++) {
            const int kc = ks * 8;
            uint32_t a[4][4];
#pragma unroll
            for (int i = 0; i < 4; i++) {
                int row = wm * 64 + i * 16 + aRow;
                ldsm4(a[i][0], a[i][1], a[i][2], a[i][3],
                      aBase + sw128(row, kc + aCol));
            }
            uint32_t bf[2][4];
#pragma unroll
            for (int p = 0; p < 2; p++) {
                int n = wn * 32 + p * 16 + bRowO;
                ldsm4(bf[p][0], bf[p][1], bf[p][2], bf[p][3],
                      bBase + sw128(n, kc + bColO));
            }
#pragma unroll
            for (int i = 0; i < 4; i++)
#pragma unroll
                for (int j = 0; j < 4; j++)
                    mma_tf32(acc[i][j], a[i],
                             bf[j >> 1][(j & 1) * 2], bf[j >> 1][(j & 1) * 2 + 1]);
        }
        if (kt + 2 < GM_KT) GM_LOAD(kt + 2);
    }

    // ---- epilogue ----
    const int g  = lane >> 2;
    const int t2 = (lane & 3) * 2;
    const int sQ = col0 >> 10;                        // 0:q 1:k 2:v
    const int h  = ((col0 + wn * 32) >> 6) & (H_ - 1);

    float rb[4][2];
#pragma unroll
    for (int j = 0; j < 4; j++) {
        rb[j][0] = __ldg(bias + col0 + wn * 32 + j * 8 + t2);
        rb[j][1] = __ldg(bias + col0 + wn * 32 + j * 8 + t2 + 1);
    }

#pragma unroll
    for (int i = 0; i < 4; i++) {
        int m    = row0 + wm * 64 + i * 16 + g;
        int bidx = m >> 11;
        int ti   = m & (T_ - 1);
#pragma unroll
        for (int j = 0; j < 4; j++) {
            int d = ((wn & 1) * 32) + j * 8 + t2;
            float c0 = acc[i][j][0] + rb[j][0];
            float c1 = acc[i][j][1] + rb[j][1];
            float c2 = acc[i][j][2] + rb[j][0];
            float c3 = acc[i][j][3] + rb[j][1];
            if (sQ == 0) {
                c0 *= 0.125f; c1 *= 0.125f; c2 *= 0.125f; c3 *= 0.125f;
            }
            c0 = to_tf32(c0); c1 = to_tf32(c1);
            c2 = to_tf32(c2); c3 = to_tf32(c3);
            if (sQ == 2) {
                float* p = g_vt + (((size_t)bidx * H_ + h) * HS_ + d) * T_ + ti;
                p[0]      = c0;  p[T_]     = c1;
                p[8]      = c2;  p[T_ + 8] = c3;
            } else {
                float* dst = (sQ == 0) ? g_q : g_k;
                float* p = dst + (((size_t)bidx * H_ + h) * T_ + ti) * HS_ + d;
                *(float2*)p             = make_float2(c0, c1);
                *(float2*)(p + 8 * HS_) = make_float2(c2, c3);
            }
        }
    }
}

// ---------------------------------------------------------------------------
// Kernel 2: causal flash attention, tf32 mma.sync.
// Br=128 (8 warps x 16 rows), Bc=64, DOUBLE-buffered K/Vt, P via register
// shuffle (no P smem). Swizzled pitch-64 smem: Q 32K + 2x(K16K+V16K) = 96KB,
// 2 CTAs/SM.
// ---------------------------------------------------------------------------
#define FA_SMEM_BYTES 98304
// float offsets: Q @0 (8192), buf s: K @8192+s*8192, V @12288+s*8192

__global__ __launch_bounds__(256, 2)
void flash_tc(float* __restrict__ out) {
    extern __shared__ float sm[];
    const uint32_t sb = smem_u32(sm);
    const int tid  = threadIdx.x;
    const int lane = tid & 31;
    const int w    = tid >> 5;
    const int bh   = blockIdx.y;
    const int b    = bh >> 4;
    const int h    = bh & (H_ - 1);
    const int qt   = gridDim.x - 1 - blockIdx.x;   // biggest first
    const int q0   = qt * 128;
    const size_t base  = (size_t)bh * T_ * HS_;
    const size_t baseV = (size_t)bh * HS_ * T_;

    const uint32_t qB = sb;

    const int lr = tid >> 4;                 // 0..15
    const int lc = (tid & 15) * 4;           // 0..60
    const int nkt = 2 * qt + 2;

#define FA_LOAD_KV(kn, s_) do {                                                \
    uint32_t kB_ = sb + (8192 + (s_) * 8192) * 4;                              \
    uint32_t vB_ = kB_ + 16384;                                                \
    _Pragma("unroll")                                                          \
    for (int p_ = 0; p_ < 4; p_++) {                                           \
        int r_ = lr + p_ * 16;                                                 \
        cp16(kB_ + sw256(r_, lc), g_k + base + (size_t)((kn) + r_) * HS_ + lc);\
        cp16(vB_ + sw256(r_, lc), g_vt + baseV + (size_t)r_ * T_ + (kn) + lc); \
    }                                                                          \
    asm volatile("cp.async.commit_group;" ::: "memory");                       \
} while (0)

    // Prologue: group0 = Q + K0/V0; group1 = K1/V1.
    {
        uint32_t kB0 = sb + 8192 * 4;
        uint32_t vB0 = kB0 + 16384;
#pragma unroll
        for (int p = 0; p < 8; p++) {
            int r = lr + p * 16;
            cp16(qB + sw256(r, lc), g_q + base + (size_t)(q0 + r) * HS_ + lc);
        }
#pragma unroll
        for (int p = 0; p < 4; p++) {
            int r = lr + p * 16;
            cp16(kB0 + sw256(r, lc), g_k + base + (size_t)r * HS_ + lc);
            cp16(vB0 + sw256(r, lc), g_vt + baseV + (size_t)r * T_ + lc);
        }
        asm volatile("cp.async.commit_group;" ::: "memory");
        FA_LOAD_KV(64, 1);
    }

    float o[8][4];
    float m_[2], l_[2];
    m_[0] = m_[1] = -1e30f;
    l_[0] = l_[1] = 0.0f;
#pragma unroll
    for (int j = 0; j < 8; j++)
#pragma unroll
        for (int e = 0; e < 4; e++) o[j][e] = 0.0f;

    const int aRow  = lane & 15;
    const int aCol  = (lane >> 4) * 4;
    const int bRowO = ((lane & 16) ? 8 : 0) + (lane & 7);
    const int bColO = (lane & 8) ? 4 : 0;
    const int g  = lane >> 2;
    const int t2 = (lane & 3) * 2;
    const int srcA  = (lane & ~3) | ((lane & 3) >> 1);
    const int srcA2 = srcA | 2;
    const bool oddL = lane & 1;

    for (int kt = 0; kt < nkt; kt++) {
        const int k0 = kt * 64;
        const int bufs = kt & 1;
        const uint32_t kB = sb + (8192 + bufs * 8192) * 4;
        const uint32_t vB = kB + 16384;

        if (kt + 1 < nkt) asm volatile("cp.async.wait_group 1;" ::: "memory");
        else              asm volatile("cp.async.wait_group 0;" ::: "memory");
        __syncthreads();

        // S = Q K^T
        float s[8][4];
#pragma unroll
        for (int j = 0; j < 8; j++)
#pragma unroll
            for (int e = 0; e < 4; e++) s[j][e] = 0.0f;

#pragma unroll
        for (int ks = 0; ks < 8; ks++) {
            const int kc = ks * 8;
            uint32_t a[4];
            ldsm4(a[0], a[1], a[2], a[3],
                  qB + sw256(w * 16 + aRow, kc + aCol));
            uint32_t bf[4][4];
#pragma unroll
            for (int p = 0; p < 4; p++)
                ldsm4(bf[p][0], bf[p][1], bf[p][2], bf[p][3],
                      kB + sw256(p * 16 + bRowO, kc + bColO));
#pragma unroll
            for (int j = 0; j < 8; j++)
                mma_tf32(s[j], a,
                         bf[j >> 1][(j & 1) * 2], bf[j >> 1][(j & 1) * 2 + 1]);
        }

        // causal mask (diagonal 128-block = last two kt's)
        if (kt >= 2 * qt) {
#pragma unroll
            for (int j = 0; j < 8; j++)
#pragma unroll
                for (int e = 0; e < 4; e++) {
                    int rg = q0 + w * 16 + g + ((e & 2) ? 8 : 0);
                    int kg = k0 + j * 8 + t2 + (e & 1);
                    if (kg > rg) s[j][e] = -1e30f;
                }
        }

        // online softmax (4-lane row groups)
#pragma unroll
        for (int hf = 0; hf < 2; hf++) {
            const int e0 = hf * 2;
            float mx = -1e30f;
#pragma unroll
            for (int j = 0; j < 8; j++)
                mx = fmaxf(mx, fmaxf(s[j][e0], s[j][e0 + 1]));
            mx = fmaxf(mx, __shfl_xor_sync(0xffffffffu, mx, 1));
            mx = fmaxf(mx, __shfl_xor_sync(0xffffffffu, mx, 2));
            float nm = fmaxf(m_[hf], mx);
            float sum = 0.0f;
#pragma unroll
            for (int j = 0; j < 8; j++) {
                s[j][e0]     = __expf(s[j][e0] - nm);
                s[j][e0 + 1] = __expf(s[j][e0 + 1] - nm);
                sum += s[j][e0] + s[j][e0 + 1];
            }
            sum += __shfl_xor_sync(0xffffffffu, sum, 1);
            sum += __shfl_xor_sync(0xffffffffu, sum, 2);
            float al = __expf(m_[hf] - nm);
            l_[hf] = l_[hf] * al + sum;
            m_[hf] = nm;
#pragma unroll
            for (int j = 0; j < 8; j++) {
                o[j][e0]     *= al;
                o[j][e0 + 1] *= al;
            }
        }

        // round P to tf32 in registers
#pragma unroll
        for (int j = 0; j < 8; j++)
#pragma unroll
            for (int e = 0; e < 4; e++) s[j][e] = to_tf32(s[j][e]);

        // O += P V: A-frag(k-chunk ks) = shuffle of s[ks] C-frag
#pragma unroll
        for (int ks = 0; ks < 8; ks++) {
            const int kc = ks * 8;
            float t00 = __shfl_sync(0xffffffffu, s[ks][0], srcA);
            float t01 = __shfl_sync(0xffffffffu, s[ks][1], srcA);
            float t02 = __shfl_sync(0xffffffffu, s[ks][2], srcA);
            float t03 = __shfl_sync(0xffffffffu, s[ks][3], srcA);
            float u00 = __shfl_sync(0xffffffffu, s[ks][0], srcA2);
            float u01 = __shfl_sync(0xffffffffu, s[ks][1], srcA2);
            float u02 = __shfl_sync(0xffffffffu, s[ks][2], srcA2);
            float u03 = __shfl_sync(0xffffffffu, s[ks][3], srcA2);
            uint32_t a[4];
            a[0] = __float_as_uint(oddL ? t01 : t00);
            a[1] = __float_as_uint(oddL ? t03 : t02);
            a[2] = __float_as_uint(oddL ? u01 : u00);
            a[3] = __float_as_uint(oddL ? u03 : u02);
            uint32_t bf[4][4];
#pragma unroll
            for (int p = 0; p < 4; p++)
                ldsm4(bf[p][0], bf[p][1], bf[p][2], bf[p][3],
                      vB + sw256(p * 16 + bRowO, kc + bColO));
#pragma unroll
            for (int j = 0; j < 8; j++)
                mma_tf32(o[j], a,
                         bf[j >> 1][(j & 1) * 2], bf[j >> 1][(j & 1) * 2 + 1]);
        }

        __syncthreads();     // all warps done reading buf before refill
        if (kt + 2 < nkt) FA_LOAD_KV(k0 + 128, bufs);
    }

    // finalize + write out[b, t, h*64 + d]
    float inv0 = 1.0f / l_[0];
    float inv1 = 1.0f / l_[1];
    int row = q0 + w * 16 + g;
#pragma unroll
    for (int j = 0; j < 8; j++) {
        int d = j * 8 + t2;
        float* p0 = out + (size_t)(b * T_ + row) * C_ + h * HS_ + d;
        *(float2*)p0            = make_float2(o[j][0] * inv0, o[j][1] * inv0);
        *(float2*)(p0 + 8 * C_) = make_float2(o[j][2] * inv1, o[j][3] * inv1);
    }
}

// ---------------------------------------------------------------------------
extern "C" void kernel_launch(void* const* d_in, const int* in_sizes, int n_in,
                              void* d_out, int out_size) {
    const float* x    = (const float*)d_in[0];
    const float* W    = (const float*)d_in[1];
    const float* bias = (const float*)d_in[2];
    float* out = (float*)d_out;

    cudaFuncSetAttribute(qkv_gemm_tc,
                         cudaFuncAttributeMaxDynamicSharedMemorySize,
                         GM_SMEM_BYTES);
    cudaFuncSetAttribute(flash_tc,
                         cudaFuncAttributeMaxDynamicSharedMemorySize,
                         FA_SMEM_BYTES);

    round_inputs<<<(NX4 + NW4) / 256, 256>>>(x, W);

    dim3 g1(N3_ / 128, M_ / 128);           // 24 x 64 = 1536 CTAs
    qkv_gemm_tc<<<g1, 256, GM_SMEM_BYTES>>>(bias);

    dim3 g2(T_ / 128, B_ * H_);             // 16 x 64 = 1024 CTAs
    flash_tc<<<g2, 256, FA_SMEM_BYTES>>>(out);
}